// round 14
// baseline (speedup 1.0000x reference)
#include <cuda_runtime.h>
#include <math.h>

// Fixed shape: N=100000, E=1600000, all dims 64.
#define MAXN 100000
#define MAXE 1600000
#define D 64

// Scratch (device globals; no allocation allowed)
__device__ float g_agg[MAXN * D];   // neighbor mean
__device__ float g_h1 [MAXN * D];
__device__ float g_h2 [MAXN * D];
__device__ int   g_deg[MAXN];
__device__ int   g_off[MAXN];
__device__ int   g_cur[MAXN];
__device__ int   g_srcidx[MAXE];
__device__ float g_invdeg[MAXN];

// ---------------------------------------------------------------------------
// CSR build
// ---------------------------------------------------------------------------
__global__ void zero_deg_kernel(int n) {
    int i = blockIdx.x * blockDim.x + threadIdx.x;
    if (i < n) g_deg[i] = 0;
}

__global__ void deg_kernel(const int* __restrict__ dst, int E) {
    int e = blockIdx.x * blockDim.x + threadIdx.x;
    if (e < E) atomicAdd(&g_deg[dst[e]], 1);
}

// Single-block exclusive scan of g_deg -> g_off/g_cur, plus invdeg.
__global__ __launch_bounds__(1024) void scan_kernel(int n) {
    __shared__ int ssum[1024];
    int t = threadIdx.x;
    int chunk = (n + 1023) >> 10;
    int beg = t * chunk;
    int end = min(beg + chunk, n);
    int s = 0;
    for (int i = beg; i < end; i++) s += g_deg[i];
    ssum[t] = s;
    __syncthreads();
    for (int off = 1; off < 1024; off <<= 1) {
        int v = (t >= off) ? ssum[t - off] : 0;
        __syncthreads();
        ssum[t] += v;
        __syncthreads();
    }
    int run = (t == 0) ? 0 : ssum[t - 1];
    for (int i = beg; i < end; i++) {
        int d = g_deg[i];
        g_off[i] = run;
        g_cur[i] = run;
        g_invdeg[i] = 1.0f / fmaxf((float)d, 1.0f);
        run += d;
    }
}

__global__ void fill_kernel(const int* __restrict__ src,
                            const int* __restrict__ dst, int E) {
    int e = blockIdx.x * blockDim.x + threadIdx.x;
    if (e < E) {
        int d = dst[e];
        int p = atomicAdd(&g_cur[d], 1);
        g_srcidx[p] = src[e];
    }
}

// ---------------------------------------------------------------------------
// Neighbor mean: one warp per node.  Lane covers 2 dims (float2 -> 256B/warp
// per neighbor, fully coalesced).  Neighbors unrolled x4 with split
// accumulators for MLP.  Pull-based: plain stores, no atomics.
// insel: 0 -> read xin, 1 -> read g_h1.
// ---------------------------------------------------------------------------
__global__ __launch_bounds__(256) void agg_kernel(
    const float* __restrict__ xin, int insel, int n)
{
    const float* in = insel ? g_h1 : xin;
    int wid = (blockIdx.x * 256 + threadIdx.x) >> 5;
    int lane = threadIdx.x & 31;
    if (wid >= n) return;

    int beg = g_off[wid];
    int cnt = g_deg[wid];
    const float2* fb = (const float2*)in;

    float ax0 = 0.f, ay0 = 0.f, ax1 = 0.f, ay1 = 0.f;
    int k = 0;
    for (; k + 4 <= cnt; k += 4) {
        int s0 = g_srcidx[beg + k];
        int s1 = g_srcidx[beg + k + 1];
        int s2 = g_srcidx[beg + k + 2];
        int s3 = g_srcidx[beg + k + 3];
        float2 v0 = fb[(long long)s0 * 32 + lane];
        float2 v1 = fb[(long long)s1 * 32 + lane];
        float2 v2 = fb[(long long)s2 * 32 + lane];
        float2 v3 = fb[(long long)s3 * 32 + lane];
        ax0 += v0.x + v1.x;  ay0 += v0.y + v1.y;
        ax1 += v2.x + v3.x;  ay1 += v2.y + v3.y;
    }
    for (; k < cnt; k++) {
        int s = g_srcidx[beg + k];
        float2 v = fb[(long long)s * 32 + lane];
        ax0 += v.x;  ay0 += v.y;
    }
    float inv = g_invdeg[wid];
    ((float2*)g_agg)[(long long)wid * 32 + lane] =
        make_float2((ax0 + ax1) * inv, (ay0 + ay1) * inv);
}

// ---------------------------------------------------------------------------
// SAGE layer GEMM: out = relu( mean@Wl^T + bl + in@Wr^T )
// Warp owns 8 nodes; lane computes output cols j=lane and j=lane+32.
// smem: sW = [Wl;Wr]^T as [k=0..127][j=0..63] pitch 65 (conflict-free);
//       sV = per-node [mean(64) | x(64)].
// insel: 0 -> read xin, 1 -> read g_h1.  outsel: 0 -> g_h1, 1 -> g_h2.
// ---------------------------------------------------------------------------
#define LAYER_SMEM_FLOATS (128 * 65 + 64 * 128)
#define LAYER_SMEM_BYTES  (LAYER_SMEM_FLOATS * 4)

__global__ __launch_bounds__(256) void layer_kernel(
    const float* __restrict__ xin, const float* __restrict__ Wl,
    const float* __restrict__ bl, const float* __restrict__ Wr,
    int insel, int outsel, int n)
{
    extern __shared__ float sm[];
    float* sW = sm;              // 128 x 65
    float* sV = sm + 128 * 65;   // 64 nodes x 128

    const float* in = insel ? g_h1 : xin;
    float* out = outsel ? g_h2 : g_h1;

    int tid = threadIdx.x;
    int lane = tid & 31;
    int w = tid >> 5;

    // Stage concatenated transposed weights: sW[k*65 + j]
    for (int idx = tid; idx < 2 * 64 * 64; idx += 256) {
        int m = idx >> 12;        // 0 -> Wl (mean), 1 -> Wr (self)
        int r = idx & 4095;       // j*64 + k (coalesced global read)
        int j = r >> 6;
        int k = r & 63;
        float wv = (m == 0) ? Wl[r] : Wr[r];
        sW[(m * 64 + k) * 65 + j] = wv;
    }
    __syncthreads();

    int base = blockIdx.x * 64 + w * 8;

    // Stage 8 node rows: [mean | x], float4 coalesced
    for (int g = 0; g < 8; g++) {
        int node = base + g;
        float4 v = make_float4(0.f, 0.f, 0.f, 0.f);
        if (node < n) {
            if (lane < 16)
                v = ((const float4*)g_agg)[(long long)node * 16 + lane];
            else
                v = ((const float4*)in)[(long long)node * 16 + (lane - 16)];
        }
        ((float4*)(sV + (w * 8 + g) * 128))[lane] = v;
    }
    __syncwarp();

    float acc[8][2];
#pragma unroll
    for (int g = 0; g < 8; g++) { acc[g][0] = 0.f; acc[g][1] = 0.f; }

    const float* vb = sV + (w * 8) * 128;
#pragma unroll 4
    for (int kk = 0; kk < 32; kk++) {
        float w0[4], w1[4];
#pragma unroll
        for (int u = 0; u < 4; u++) {
            w0[u] = sW[(kk * 4 + u) * 65 + lane];
            w1[u] = sW[(kk * 4 + u) * 65 + 32 + lane];
        }
#pragma unroll
        for (int g = 0; g < 8; g++) {
            float4 v = *(const float4*)(vb + g * 128 + kk * 4);  // broadcast
            acc[g][0] += v.x * w0[0] + v.y * w0[1] + v.z * w0[2] + v.w * w0[3];
            acc[g][1] += v.x * w1[0] + v.y * w1[1] + v.z * w1[2] + v.w * w1[3];
        }
    }

    float b0 = bl[lane];
    float b1 = bl[32 + lane];
#pragma unroll
    for (int g = 0; g < 8; g++) {
        int node = base + g;
        if (node < n) {
            out[(long long)node * 64 + lane]      = fmaxf(acc[g][0] + b0, 0.f);
            out[(long long)node * 64 + 32 + lane] = fmaxf(acc[g][1] + b1, 0.f);
        }
    }
}

// ---------------------------------------------------------------------------
// Output head: logits = h2 @ Wout^T + bout; out = log_softmax(logits)
// ---------------------------------------------------------------------------
__global__ __launch_bounds__(256) void out_kernel(
    const float* __restrict__ Wout, const float* __restrict__ bout,
    float* __restrict__ out, int n)
{
    __shared__ __align__(16) float sW[64 * 65];
    __shared__ __align__(16) float sV[64 * 64];

    int tid = threadIdx.x;
    int lane = tid & 31;
    int w = tid >> 5;

    for (int idx = tid; idx < 64 * 64; idx += 256) {
        int j = idx >> 6;
        int k = idx & 63;
        sW[k * 65 + j] = Wout[idx];
    }

    int base = blockIdx.x * 64 + w * 8;

    for (int p = 0; p < 4; p++) {
        int g = p * 2 + (lane >> 4);
        int node = base + g;
        int q = lane & 15;
        float4 v = make_float4(0.f, 0.f, 0.f, 0.f);
        if (node < n) v = ((const float4*)g_h2)[(long long)node * 16 + q];
        ((float4*)(sV + (w * 8 + g) * 64))[q] = v;
    }
    __syncthreads();

    float acc[8][2];
#pragma unroll
    for (int g = 0; g < 8; g++) { acc[g][0] = 0.f; acc[g][1] = 0.f; }

    const float* vb = sV + (w * 8) * 64;
#pragma unroll 4
    for (int kk = 0; kk < 16; kk++) {
        float w0[4], w1[4];
#pragma unroll
        for (int u = 0; u < 4; u++) {
            w0[u] = sW[(kk * 4 + u) * 65 + lane];
            w1[u] = sW[(kk * 4 + u) * 65 + 32 + lane];
        }
#pragma unroll
        for (int g = 0; g < 8; g++) {
            float4 v = *(const float4*)(vb + g * 64 + kk * 4);
            acc[g][0] += v.x * w0[0] + v.y * w0[1] + v.z * w0[2] + v.w * w0[3];
            acc[g][1] += v.x * w1[0] + v.y * w1[1] + v.z * w1[2] + v.w * w1[3];
        }
    }

    float b0 = bout[lane];
    float b1 = bout[32 + lane];
#pragma unroll
    for (int g = 0; g < 8; g++) {
        int node = base + g;
        float l0 = acc[g][0] + b0;
        float l1 = acc[g][1] + b1;
        float m = fmaxf(l0, l1);
#pragma unroll
        for (int o = 16; o; o >>= 1) m = fmaxf(m, __shfl_xor_sync(0xffffffffu, m, o));
        float s = expf(l0 - m) + expf(l1 - m);
#pragma unroll
        for (int o = 16; o; o >>= 1) s += __shfl_xor_sync(0xffffffffu, s, o);
        float lse = m + logf(s);
        if (node < n) {
            out[(long long)node * 64 + lane]      = l0 - lse;
            out[(long long)node * 64 + 32 + lane] = l1 - lse;
        }
    }
}

// ---------------------------------------------------------------------------
// Launch
// ---------------------------------------------------------------------------
extern "C" void kernel_launch(void* const* d_in, const int* in_sizes, int n_in,
                              void* d_out, int out_size) {
    const float* x        = (const float*)d_in[0];
    const int*   ei       = (const int*)d_in[1];   // int32 (JAX x64 disabled)
    const float* W1l      = (const float*)d_in[2];
    const float* b1l      = (const float*)d_in[3];
    const float* W1r      = (const float*)d_in[4];
    const float* W2l      = (const float*)d_in[5];
    const float* b2l      = (const float*)d_in[6];
    const float* W2r      = (const float*)d_in[7];
    const float* Wout     = (const float*)d_in[8];
    const float* bout     = (const float*)d_in[9];
    float* out            = (float*)d_out;

    int n = in_sizes[0] / D;
    int E = in_sizes[1] / 2;
    const int* src = ei;        // row 0
    const int* dst = ei + E;    // row 1

    cudaFuncSetAttribute(layer_kernel,
                         cudaFuncAttributeMaxDynamicSharedMemorySize,
                         LAYER_SMEM_BYTES);

    int egrid = (E + 255) / 256;
    int ngrid = (n + 255) / 256;
    int lgrid = (n + 63) / 64;
    int agrid = (n + 7) / 8;   // 8 warps (nodes) per 256-thread block

    // CSR build (shared by both layers)
    zero_deg_kernel<<<ngrid, 256>>>(n);
    deg_kernel<<<egrid, 256>>>(dst, E);
    scan_kernel<<<1, 1024>>>(n);
    fill_kernel<<<egrid, 256>>>(src, dst, E);

    // Layer 1
    agg_kernel<<<agrid, 256>>>(x, 0, n);
    layer_kernel<<<lgrid, 256, LAYER_SMEM_BYTES>>>(x, W1l, b1l, W1r, 0, 0, n);

    // Layer 2
    agg_kernel<<<agrid, 256>>>(x, 1, n);
    layer_kernel<<<lgrid, 256, LAYER_SMEM_BYTES>>>(x, W2l, b2l, W2r, 1, 1, n);

    // Output head + log-softmax
    out_kernel<<<lgrid, 256>>>(Wout, bout, out, n);
}

// round 15
// speedup vs baseline: 1.6461x; 1.6461x over previous
#include <cuda_runtime.h>
#include <math.h>

// Fixed shape: N=100000, E=1600000, all dims 64.
#define MAXN 100000
#define MAXE 1600000
#define D 64
#define SCAN_B 1024
#define NBLK 128   // >= ceil(MAXN/SCAN_B) = 98

// Scratch (device globals; no allocation allowed)
__device__ float g_h1 [MAXN * D];
__device__ float g_h2 [MAXN * D];
__device__ int   g_deg[MAXN];
__device__ int   g_off[MAXN];
__device__ int   g_cur[MAXN];
__device__ int   g_srcidx[MAXE];
__device__ float g_invdeg[MAXN];
__device__ int   g_blocksum[NBLK];
__device__ int   g_blockoff[NBLK];

// ---------------------------------------------------------------------------
// CSR build
// ---------------------------------------------------------------------------
__global__ void zero_deg_kernel(int n) {
    int i = blockIdx.x * blockDim.x + threadIdx.x;
    if (i < n) g_deg[i] = 0;
}

__global__ void deg_kernel(const int* __restrict__ dst, int E) {
    int e = blockIdx.x * blockDim.x + threadIdx.x;
    if (e < E) atomicAdd(&g_deg[dst[e]], 1);
}

// Phase A: coalesced per-block reduction of deg
__global__ __launch_bounds__(SCAN_B) void scanA_kernel(int n) {
    int i = blockIdx.x * SCAN_B + threadIdx.x;
    int v = (i < n) ? g_deg[i] : 0;
#pragma unroll
    for (int o = 16; o; o >>= 1) v += __shfl_xor_sync(0xffffffffu, v, o);
    __shared__ int ws[32];
    if ((threadIdx.x & 31) == 0) ws[threadIdx.x >> 5] = v;
    __syncthreads();
    if (threadIdx.x < 32) {
        int s = ws[threadIdx.x];
#pragma unroll
        for (int o = 16; o; o >>= 1) s += __shfl_xor_sync(0xffffffffu, s, o);
        if (threadIdx.x == 0) g_blocksum[blockIdx.x] = s;
    }
}

// Phase B: single-block exclusive scan of block sums
__global__ __launch_bounds__(NBLK) void scanB_kernel(int nb) {
    __shared__ int s[NBLK];
    int t = threadIdx.x;
    int v = (t < nb) ? g_blocksum[t] : 0;
    s[t] = v;
    __syncthreads();
    for (int o = 1; o < NBLK; o <<= 1) {
        int u = (t >= o) ? s[t - o] : 0;
        __syncthreads();
        s[t] += u;
        __syncthreads();
    }
    g_blockoff[t] = s[t] - v;   // exclusive
}

// Phase C: per-block exclusive scan + offset; emits off/cur/invdeg (coalesced)
__global__ __launch_bounds__(SCAN_B) void scanC_kernel(int n) {
    __shared__ int sm[SCAN_B];
    int i = blockIdx.x * SCAN_B + threadIdx.x;
    int t = threadIdx.x;
    int v = (i < n) ? g_deg[i] : 0;
    sm[t] = v;
    __syncthreads();
    for (int o = 1; o < SCAN_B; o <<= 1) {
        int u = (t >= o) ? sm[t - o] : 0;
        __syncthreads();
        sm[t] += u;
        __syncthreads();
    }
    if (i < n) {
        int excl = sm[t] - v + g_blockoff[blockIdx.x];
        g_off[i] = excl;
        g_cur[i] = excl;
        g_invdeg[i] = 1.0f / fmaxf((float)v, 1.0f);
    }
}

__global__ void fill_kernel(const int* __restrict__ src,
                            const int* __restrict__ dst, int E) {
    int e = blockIdx.x * blockDim.x + threadIdx.x;
    if (e < E) {
        int d = dst[e];
        int p = atomicAdd(&g_cur[d], 1);
        g_srcidx[p] = src[e];
    }
}

// ---------------------------------------------------------------------------
// Fused SAGE layer: mean-gather (CSR) + out = relu(mean@Wl^T + bl + in@Wr^T)
// Warp owns 8 nodes; lane computes output cols j=lane and j=lane+32.
// smem: sW = [Wl;Wr]^T as [k=0..127][j=0..63] pitch 65 (conflict-free);
//       sV = per-node [mean(64) | x(64)].
// insel: 0 -> read xin, 1 -> read g_h1.  outsel: 0 -> g_h1, 1 -> g_h2.
// ---------------------------------------------------------------------------
#define LAYER_SMEM_FLOATS (128 * 65 + 64 * 128)
#define LAYER_SMEM_BYTES  (LAYER_SMEM_FLOATS * 4)

__global__ __launch_bounds__(256) void layer_kernel(
    const float* __restrict__ xin, const float* __restrict__ Wl,
    const float* __restrict__ bl, const float* __restrict__ Wr,
    int insel, int outsel, int n)
{
    extern __shared__ float sm[];
    float* sW = sm;              // 128 x 65
    float* sV = sm + 128 * 65;   // 64 nodes x 128

    const float* in = insel ? g_h1 : xin;
    float* out = outsel ? g_h2 : g_h1;

    int tid = threadIdx.x;
    int lane = tid & 31;
    int w = tid >> 5;

    // Stage concatenated transposed weights: sW[k*65 + j]
    for (int idx = tid; idx < 2 * 64 * 64; idx += 256) {
        int m = idx >> 12;        // 0 -> Wl, 1 -> Wr
        int r = idx & 4095;       // j*64 + k (coalesced global read)
        int j = r >> 6;
        int k = r & 63;
        float wv = (m == 0) ? Wl[r] : Wr[r];
        sW[(m * 64 + k) * 65 + j] = wv;
    }
    __syncthreads();

    int base = blockIdx.x * 64 + w * 8;

    // Stage 8 node rows: [mean | x], mean via CSR neighbor gather
    for (int g = 0; g < 8; g++) {
        int node = base + g;
        float* row = sV + (w * 8 + g) * 128;
        if (node < n) {
            int beg = g_off[node];
            int cnt = g_deg[node];
            float a0 = 0.f, a1 = 0.f;
            int k = 0;
            for (; k + 1 < cnt; k += 2) {
                int s0 = g_srcidx[beg + k];
                int s1 = g_srcidx[beg + k + 1];
                float v00 = in[(long long)s0 * 64 + lane];
                float v01 = in[(long long)s0 * 64 + 32 + lane];
                float v10 = in[(long long)s1 * 64 + lane];
                float v11 = in[(long long)s1 * 64 + 32 + lane];
                a0 += v00 + v10;
                a1 += v01 + v11;
            }
            if (k < cnt) {
                int s0 = g_srcidx[beg + k];
                a0 += in[(long long)s0 * 64 + lane];
                a1 += in[(long long)s0 * 64 + 32 + lane];
            }
            float inv = g_invdeg[node];
            row[lane]      = a0 * inv;
            row[32 + lane] = a1 * inv;
            row[64 + lane] = in[(long long)node * 64 + lane];
            row[96 + lane] = in[(long long)node * 64 + 32 + lane];
        } else {
            row[lane] = 0.f; row[32 + lane] = 0.f;
            row[64 + lane] = 0.f; row[96 + lane] = 0.f;
        }
    }
    __syncwarp();

    float acc[8][2];
#pragma unroll
    for (int g = 0; g < 8; g++) { acc[g][0] = 0.f; acc[g][1] = 0.f; }

    const float* vb = sV + (w * 8) * 128;
#pragma unroll 4
    for (int kk = 0; kk < 32; kk++) {
        float w0[4], w1[4];
#pragma unroll
        for (int u = 0; u < 4; u++) {
            w0[u] = sW[(kk * 4 + u) * 65 + lane];
            w1[u] = sW[(kk * 4 + u) * 65 + 32 + lane];
        }
#pragma unroll
        for (int g = 0; g < 8; g++) {
            float4 v = *(const float4*)(vb + g * 128 + kk * 4);  // broadcast
            acc[g][0] += v.x * w0[0] + v.y * w0[1] + v.z * w0[2] + v.w * w0[3];
            acc[g][1] += v.x * w1[0] + v.y * w1[1] + v.z * w1[2] + v.w * w1[3];
        }
    }

    float b0 = bl[lane];
    float b1 = bl[32 + lane];
#pragma unroll
    for (int g = 0; g < 8; g++) {
        int node = base + g;
        if (node < n) {
            out[(long long)node * 64 + lane]      = fmaxf(acc[g][0] + b0, 0.f);
            out[(long long)node * 64 + 32 + lane] = fmaxf(acc[g][1] + b1, 0.f);
        }
    }
}

// ---------------------------------------------------------------------------
// Output head: logits = h2 @ Wout^T + bout; out = log_softmax(logits)
// ---------------------------------------------------------------------------
__global__ __launch_bounds__(256) void out_kernel(
    const float* __restrict__ Wout, const float* __restrict__ bout,
    float* __restrict__ out, int n)
{
    __shared__ __align__(16) float sW[64 * 65];
    __shared__ __align__(16) float sV[64 * 64];

    int tid = threadIdx.x;
    int lane = tid & 31;
    int w = tid >> 5;

    for (int idx = tid; idx < 64 * 64; idx += 256) {
        int j = idx >> 6;
        int k = idx & 63;
        sW[k * 65 + j] = Wout[idx];
    }

    int base = blockIdx.x * 64 + w * 8;

    for (int p = 0; p < 4; p++) {
        int g = p * 2 + (lane >> 4);
        int node = base + g;
        int q = lane & 15;
        float4 v = make_float4(0.f, 0.f, 0.f, 0.f);
        if (node < n) v = ((const float4*)g_h2)[(long long)node * 16 + q];
        ((float4*)(sV + (w * 8 + g) * 64))[q] = v;
    }
    __syncthreads();

    float acc[8][2];
#pragma unroll
    for (int g = 0; g < 8; g++) { acc[g][0] = 0.f; acc[g][1] = 0.f; }

    const float* vb = sV + (w * 8) * 64;
#pragma unroll 4
    for (int kk = 0; kk < 16; kk++) {
        float w0[4], w1[4];
#pragma unroll
        for (int u = 0; u < 4; u++) {
            w0[u] = sW[(kk * 4 + u) * 65 + lane];
            w1[u] = sW[(kk * 4 + u) * 65 + 32 + lane];
        }
#pragma unroll
        for (int g = 0; g < 8; g++) {
            float4 v = *(const float4*)(vb + g * 64 + kk * 4);
            acc[g][0] += v.x * w0[0] + v.y * w0[1] + v.z * w0[2] + v.w * w0[3];
            acc[g][1] += v.x * w1[0] + v.y * w1[1] + v.z * w1[2] + v.w * w1[3];
        }
    }

    float b0 = bout[lane];
    float b1 = bout[32 + lane];
#pragma unroll
    for (int g = 0; g < 8; g++) {
        int node = base + g;
        float l0 = acc[g][0] + b0;
        float l1 = acc[g][1] + b1;
        float m = fmaxf(l0, l1);
#pragma unroll
        for (int o = 16; o; o >>= 1) m = fmaxf(m, __shfl_xor_sync(0xffffffffu, m, o));
        float s = expf(l0 - m) + expf(l1 - m);
#pragma unroll
        for (int o = 16; o; o >>= 1) s += __shfl_xor_sync(0xffffffffu, s, o);
        float lse = m + logf(s);
        if (node < n) {
            out[(long long)node * 64 + lane]      = l0 - lse;
            out[(long long)node * 64 + 32 + lane] = l1 - lse;
        }
    }
}

// ---------------------------------------------------------------------------
// Launch
// ---------------------------------------------------------------------------
extern "C" void kernel_launch(void* const* d_in, const int* in_sizes, int n_in,
                              void* d_out, int out_size) {
    const float* x        = (const float*)d_in[0];
    const int*   ei       = (const int*)d_in[1];   // int32 (JAX x64 disabled)
    const float* W1l      = (const float*)d_in[2];
    const float* b1l      = (const float*)d_in[3];
    const float* W1r      = (const float*)d_in[4];
    const float* W2l      = (const float*)d_in[5];
    const float* b2l      = (const float*)d_in[6];
    const float* W2r      = (const float*)d_in[7];
    const float* Wout     = (const float*)d_in[8];
    const float* bout     = (const float*)d_in[9];
    float* out            = (float*)d_out;

    int n = in_sizes[0] / D;
    int E = in_sizes[1] / 2;
    const int* src = ei;        // row 0
    const int* dst = ei + E;    // row 1

    cudaFuncSetAttribute(layer_kernel,
                         cudaFuncAttributeMaxDynamicSharedMemorySize,
                         LAYER_SMEM_BYTES);

    int egrid = (E + 255) / 256;
    int ngrid = (n + 255) / 256;
    int lgrid = (n + 63) / 64;
    int sgrid = (n + SCAN_B - 1) / SCAN_B;   // 98 blocks

    // CSR build (shared by both layers) — parallel coalesced scan
    zero_deg_kernel<<<ngrid, 256>>>(n);
    deg_kernel<<<egrid, 256>>>(dst, E);
    scanA_kernel<<<sgrid, SCAN_B>>>(n);
    scanB_kernel<<<1, NBLK>>>(sgrid);
    scanC_kernel<<<sgrid, SCAN_B>>>(n);
    fill_kernel<<<egrid, 256>>>(src, dst, E);

    // Fused layers
    layer_kernel<<<lgrid, 256, LAYER_SMEM_BYTES>>>(x, W1l, b1l, W1r, 0, 0, n);
    layer_kernel<<<lgrid, 256, LAYER_SMEM_BYTES>>>(x, W2l, b2l, W2r, 1, 1, n);

    // Output head + log-softmax
    out_kernel<<<lgrid, 256>>>(Wout, bout, out, n);
}